// round 14
// baseline (speedup 1.0000x reference)
#include <cuda_runtime.h>
#include <cuda_bf16.h>
#include <math.h>

#define Tt 128
#define Bb 32
#define PH 256
#define WH 1024
#define PV 45
#define WV 32000
#define PE 64
#define WE 512
#define GRID 128

// ---------------- device scratch (no allocations) ----------------
__device__ float g_Apos[Tt*Bb*4*PH];
__device__ float g_Aw0 [Tt*Bb*4*WH];
__device__ float g_ph  [(Tt+1)*Bb*PH];
__device__ float g_wh0 [(Tt+1)*Bb*WH];
__device__ float g_wh1 [(Tt+1)*Bb*WH];
__device__ float g_pc  [Bb*PH];
__device__ float g_wc0 [Bb*WH];
__device__ float g_wc1 [Bb*WH];
__device__ float g_wmid[Tt*Bb*WE];
__device__ __nv_bfloat16 g_embH[WV*WE];
__device__ __nv_bfloat16 g_embL[WV*WE];
__device__ __nv_bfloat16 g_midH[Tt*Bb*WE];
__device__ __nv_bfloat16 g_midL[Tt*Bb*WE];
__device__ unsigned g_cnt;
__device__ volatile unsigned g_gen;

// ---------------- generic helpers ----------------
__device__ __forceinline__ unsigned long long fma2(unsigned long long a,
                                                   unsigned long long b,
                                                   unsigned long long c) {
    unsigned long long d;
    asm("fma.rn.f32x2 %0, %1, %2, %3;" : "=l"(d) : "l"(a), "l"(b), "l"(c));
    return d;
}
__device__ __forceinline__ float acc_sum(unsigned long long v) {
    float x, y;
    asm("mov.b64 {%0,%1}, %2;" : "=f"(x), "=f"(y) : "l"(v));
    return x + y;
}
__device__ __forceinline__ float sigf(float x) { return 1.0f / (1.0f + expf(-x)); }

__device__ __forceinline__ void cp16(void* s, const void* g) {
    unsigned ss = (unsigned)__cvta_generic_to_shared(s);
    asm volatile("cp.async.cg.shared.global [%0], [%1], 16;" :: "r"(ss), "l"(g));
}
__device__ __forceinline__ void cp_commit() {
    asm volatile("cp.async.commit_group;" ::: "memory");
}
template <int N> __device__ __forceinline__ void cp_wait() {
    asm volatile("cp.async.wait_group %0;" :: "n"(N) : "memory");
}
__device__ __forceinline__ unsigned smem_u32(const void* p) {
    return (unsigned)__cvta_generic_to_shared(p);
}

// mma.sync bf16 + ldmatrix (non-arch-gated tensor path, works on sm_103)
__device__ __forceinline__ void ldsm4(unsigned r[4], unsigned addr) {
    asm volatile("ldmatrix.sync.aligned.m8n8.x4.shared.b16 {%0,%1,%2,%3}, [%4];"
        : "=r"(r[0]), "=r"(r[1]), "=r"(r[2]), "=r"(r[3]) : "r"(addr));
}
__device__ __forceinline__ void ldsm2(unsigned r[2], unsigned addr) {
    asm volatile("ldmatrix.sync.aligned.m8n8.x2.shared.b16 {%0,%1}, [%2];"
        : "=r"(r[0]), "=r"(r[1]) : "r"(addr));
}
__device__ __forceinline__ void mma16816(float c[4], const unsigned a[4], const unsigned b[2]) {
    asm volatile("mma.sync.aligned.m16n8k16.row.col.f32.bf16.bf16.f32 "
        "{%0,%1,%2,%3}, {%4,%5,%6,%7}, {%8,%9}, {%0,%1,%2,%3};"
        : "+f"(c[0]), "+f"(c[1]), "+f"(c[2]), "+f"(c[3])
        : "r"(a[0]), "r"(a[1]), "r"(a[2]), "r"(a[3]), "r"(b[0]), "r"(b[1]));
}

// sense-reversing grid barrier (all GRID CTAs co-resident: 1 CTA/SM)
__device__ __forceinline__ void gsync() {
    __syncthreads();
    if (threadIdx.x == 0) {
        unsigned gen = g_gen;
        __threadfence();
        if (atomicAdd(&g_cnt, 1u) == GRID - 1u) {
            g_cnt = 0u;
            __threadfence();
            g_gen = gen + 1u;
        } else {
            while (g_gen == gen) { }
        }
        __threadfence();
    }
    __syncthreads();
}

// ---------------- init ----------------
__global__ void zero_init() {
    int i = blockIdx.x * blockDim.x + threadIdx.x;
    if (i == 0) { g_cnt = 0u; g_gen = 0u; }
    if (i < Bb*PH) { g_ph[i] = 0.f; g_pc[i] = 0.f; }
    if (i < Bb*WH) { g_wh0[i] = 0.f; g_wh1[i] = 0.f; g_wc0[i] = 0.f; g_wc1[i] = 0.f; }
}

// ---------------- fp32 -> bf16 hi/lo split ----------------
__global__ void cvt_hilo(const float* __restrict__ src,
                         __nv_bfloat16* __restrict__ hi,
                         __nv_bfloat16* __restrict__ lo, int n)
{
    int i = blockIdx.x * blockDim.x + threadIdx.x;
    if (i < n) {
        float v = src[i];
        __nv_bfloat16 h = __float2bfloat16(v);
        hi[i] = h;
        lo[i] = __float2bfloat16(v - __bfloat162float(h));
    }
}

// ---------------- 4-stage pipelined NT GEMM (fp32, for precompute/wmid) ----------------
__global__ __launch_bounds__(256) void gemm_nt(
    const float* __restrict__ A, const int* __restrict__ gather, int lda,
    const float* __restrict__ Bm, int ldb,
    float* __restrict__ C, int ldc, int K,
    const float* __restrict__ bias1, const float* __restrict__ bias2)
{
    constexpr int S = 4;
    __shared__ __align__(16) float As[S][64][20];
    __shared__ __align__(16) float Bs[S][64][20];
    const int tid = threadIdx.x;
    const int m0 = blockIdx.y * 64, n0 = blockIdx.x * 64;
    const int tn = tid & 15, tm = tid >> 4;
    const int lrow = tid >> 2, lks = tid & 3;
    const int agr = gather ? gather[m0 + lrow] : (m0 + lrow);
    const float* aptr = A  + (size_t)agr * lda + lks * 4;
    const float* bptr = Bm + (size_t)(n0 + lrow) * ldb + lks * 4;

    unsigned long long acc[4][4];
#pragma unroll
    for (int r = 0; r < 4; r++)
#pragma unroll
        for (int s = 0; s < 4; s++) acc[r][s] = 0ull;

    const int nch = K >> 4;
#pragma unroll
    for (int i = 0; i < S - 1; i++) {
        if (i < nch) {
            cp16(&As[i][lrow][lks*4], aptr + i*16);
            cp16(&Bs[i][lrow][lks*4], bptr + i*16);
        }
        cp_commit();
    }

    for (int ci = 0; ci < nch; ci++) {
        if (ci + S - 1 < nch) {
            const int b = (ci + S - 1) & (S - 1);
            cp16(&As[b][lrow][lks*4], aptr + (ci + S - 1)*16);
            cp16(&Bs[b][lrow][lks*4], bptr + (ci + S - 1)*16);
            cp_commit();
            cp_wait<S-1>();
        } else {
            cp_wait<0>();
        }
        __syncthreads();
        const int bf = ci & (S - 1);
#pragma unroll
        for (int kk = 0; kk < 16; kk += 4) {
            ulonglong2 av[4], bv[4];
#pragma unroll
            for (int r = 0; r < 4; r++) av[r] = *(const ulonglong2*)&As[bf][tm*4 + r][kk];
#pragma unroll
            for (int s = 0; s < 4; s++) bv[s] = *(const ulonglong2*)&Bs[bf][tn + 16*s][kk];
#pragma unroll
            for (int r = 0; r < 4; r++)
#pragma unroll
                for (int s = 0; s < 4; s++) {
                    acc[r][s] = fma2(av[r].x, bv[s].x, acc[r][s]);
                    acc[r][s] = fma2(av[r].y, bv[s].y, acc[r][s]);
                }
        }
        __syncthreads();
    }
#pragma unroll
    for (int s = 0; s < 4; s++) {
        int n = n0 + tn + 16*s;
        float badd = 0.f;
        if (bias1) badd += bias1[n];
        if (bias2) badd += bias2[n];
#pragma unroll
        for (int r = 0; r < 4; r++) {
            int m = m0 + tm*4 + r;
            C[(size_t)m * ldc + n] = acc_sum(acc[r][s]) + badd;
        }
    }
}

// ---------------- LSTM cell phase: 16 warps = 8 k-regions x 2 col-halves ----------------
// CTA owns 32 gate cols (8 h x 4 gates). Thread tile 4 rows x 4 cols.
// Same chunk partitioning / load mapping / reduction order as R12 (bit-identical).
__device__ __noinline__ void cell_phase(
    float* smem,
    const float* pre, const float* bih, const float* bhh,
    const float* x0, int ldx0, const float* W0, int ldW0, int K0,
    const float* x1, int ldx1, const float* W1, int ldW1, int K1,
    float* c_st, float* h_out, int H)
{
    const int cta = blockIdx.x;
    if (cta * 8 >= H) return;
    const int tid  = threadIdx.x;
    const int lane = tid & 31;
    const int wid  = tid >> 5;        // 0..15
    const int kreg = wid >> 1;        // k-region 0..7
    const int chal = wid & 1;         // column half 0/1
    const int rg   = lane >> 2;       // 8 row groups (4 rows each)
    const int cq   = lane & 3;        // 4 col quads (4 cols each)
    const int cb   = chal*16 + cq*4;  // first owned col

    float* xs = smem;                 // [2][8][32][32]
    float* ws = smem + 2*8*32*32;

    const int nc0 = K0 >> 5;
    const int nch = nc0 + (K1 >> 5);
    const int cpw = nch >> 3;

    // preload pre/bias for pointwise (threads 0..255 -> (b, h) pairs)
    const int pb = tid >> 3, phh = tid & 7;
    const int hmy = cta * 8 + phh;
    float pv[4];
    if (tid < 256) {
#pragma unroll
        for (int gt = 0; gt < 4; gt++) {
            if (pre) pv[gt] = pre[(size_t)pb * (4*H) + gt*H + hmy];
            else     pv[gt] = bih[gt*H + hmy] + bhh[gt*H + hmy];
        }
    }

    unsigned long long acc[4][4];
#pragma unroll
    for (int r = 0; r < 4; r++)
#pragma unroll
        for (int c = 0; c < 4; c++) acc[r][c] = 0ull;

    auto load_stage = [&](int st, int cs) {
#pragma unroll
        for (int i = 0; i < 4; i++) {
            int idx = tid + (i << 9);          // 0..2047
            int wslot = idx >> 8;              // k-region 0..7
            int rem = idx & 255;
            int row = rem >> 3, ks = rem & 7;
            int ci = wslot * cpw + cs;
            const float* xp; const float* Wp; int ldx, ldW, k0;
            if (ci < nc0) { xp = x0; Wp = W0; ldx = ldx0; ldW = ldW0; k0 = ci << 5; }
            else          { xp = x1; Wp = W1; ldx = ldx1; ldW = ldW1; k0 = (ci - nc0) << 5; }
            cp16(&xs[((st*8 + wslot)*32 + row)*32 + ((ks ^ (row >> 2)) << 2)],
                 xp + (size_t)row * ldx + k0 + (ks << 2));
            int jr = (row >> 3) * H + cta * 8 + (row & 7);
            cp16(&ws[((st*8 + wslot)*32 + row)*32 + ((ks ^ (row >> 3)) << 2)],
                 Wp + (size_t)jr * ldW + k0 + (ks << 2));
        }
        cp_commit();
    };

    load_stage(0, 0);
    for (int cs = 0; cs < cpw; cs++) {
        if (cs + 1 < cpw) { load_stage((cs + 1) & 1, cs + 1); cp_wait<1>(); }
        else              { cp_wait<0>(); }
        __syncthreads();
        const int st = cs & 1;
        const float* xb = &xs[((st*8 + kreg)*32)*32];
        const float* wb = &ws[((st*8 + kreg)*32)*32];
#pragma unroll
        for (int kkq = 0; kkq < 8; kkq++) {
            ulonglong2 xv[4];
#pragma unroll
            for (int r = 0; r < 4; r++)
                xv[r] = *(const ulonglong2*)&xb[(rg*4 + r)*32 + ((kkq ^ rg) << 2)];
#pragma unroll
            for (int c = 0; c < 4; c++) {
                const int col = cb + c;
                ulonglong2 wv = *(const ulonglong2*)&wb[col*32 + ((kkq ^ (col >> 3)) << 2)];
#pragma unroll
                for (int r = 0; r < 4; r++) {
                    acc[r][c] = fma2(xv[r].x, wv.x, acc[r][c]);
                    acc[r][c] = fma2(xv[r].y, wv.y, acc[r][c]);
                }
            }
        }
        __syncthreads();
    }

    // deterministic 8-way k-reduction (same order as R12), then pointwise
    float* red = smem;   // overlay; mainloop ended with __syncthreads
#pragma unroll
    for (int r = 0; r < 4; r++)
#pragma unroll
        for (int c = 0; c < 4; c++)
            red[(kreg*32 + rg*4 + r)*33 + cb + c] = acc_sum(acc[r][c]);
    __syncthreads();

    if (tid < 256) {
        float g4[4];
#pragma unroll
        for (int gt = 0; gt < 4; gt++) {
            int col = gt*8 + phh;
            float v = 0.f;
#pragma unroll
            for (int w = 0; w < 8; w++) v += red[(w*32 + pb)*33 + col];
            g4[gt] = v + pv[gt];
        }
        float cp = c_st[pb*H + hmy];
        float cn = sigf(g4[1]) * cp + sigf(g4[0]) * tanhf(g4[2]);
        c_st[pb*H + hmy]  = cn;
        h_out[pb*H + hmy] = sigf(g4[3]) * tanhf(cn);
    }
    __syncthreads();   // protect overlay before next phase's loads
}

// ---------------- persistent recurrence kernel ----------------
__global__ __launch_bounds__(512, 1) void recurrence(
    const float* __restrict__ pre_pos, const float* __restrict__ pre_w0,
    const float* __restrict__ pWih,  const float* __restrict__ pWhh,
    const float* __restrict__ w0Wih, const float* __restrict__ w0Whh,
    const float* __restrict__ w1Wih, const float* __restrict__ w1Whh,
    const float* __restrict__ w1bih, const float* __restrict__ w1bhh)
{
    extern __shared__ float smem[];
    for (int t = 0; t < Tt; t++) {
        cell_phase(smem, pre_pos + (size_t)t * Bb * 4 * PH, nullptr, nullptr,
                   g_wh1 + (size_t)t * Bb * WH, WH, pWih + PE, PE + WH, WH,
                   g_ph  + (size_t)t * Bb * PH, PH, pWhh,      PH,      PH,
                   g_pc, g_ph + (size_t)(t+1) * Bb * PH, PH);
        gsync();
        cell_phase(smem, pre_w0 + (size_t)t * Bb * 4 * WH, nullptr, nullptr,
                   g_ph  + (size_t)(t+1) * Bb * PH, PH, w0Wih + WE, WE + PH, PH,
                   g_wh0 + (size_t)t * Bb * WH,     WH, w0Whh,      WH,      WH,
                   g_wc0, g_wh0 + (size_t)(t+1) * Bb * WH, WH);
        gsync();
        cell_phase(smem, nullptr, w1bih, w1bhh,
                   g_wh0 + (size_t)(t+1) * Bb * WH, WH, w1Wih, WH, WH,
                   g_wh1 + (size_t)t * Bb * WH,     WH, w1Whh, WH, WH,
                   g_wc1, g_wh1 + (size_t)(t+1) * Bb * WH, WH);
        gsync();
    }
}

// ---------------- bf16 mma.sync head GEMM ----------------
// C[4096, 32000] = A . B^T + bias via 3-term hi/lo split (Ah.Bh + Ah.Bl + Al.Bh).
// CTA tile 128x128, 8 warps (2m x 4n), warp tile 64x32 (m16n8k16 frags 4x4).
// K chunks of 32, double-buffered cp.async; smem rows padded to 80B so every
// ldmatrix phase is bank-conflict-free. Grid (m=32, n=250), m-fastest for B reuse.
#define HROW 40
__global__ __launch_bounds__(256) void head_mma(
    const __nv_bfloat16* __restrict__ Ah, const __nv_bfloat16* __restrict__ Al,
    const __nv_bfloat16* __restrict__ Bh, const __nv_bfloat16* __restrict__ Bl,
    const float* __restrict__ bias, float* __restrict__ C)
{
    extern __shared__ __align__(16) __nv_bfloat16 hsm[];
    const int tid = threadIdx.x, lane = tid & 31, wid = tid >> 5;
    const int wm = wid >> 2, wn = wid & 3;
    const int m0 = blockIdx.x * 128, n0 = blockIdx.y * 128;

    const __nv_bfloat16* srcs[4] = { Ah + (size_t)m0 * WE, Al + (size_t)m0 * WE,
                                     Bh + (size_t)n0 * WE, Bl + (size_t)n0 * WE };

    float acc[4][4][4];
#pragma unroll
    for (int mf = 0; mf < 4; mf++)
#pragma unroll
        for (int nf = 0; nf < 4; nf++)
#pragma unroll
            for (int i = 0; i < 4; i++) acc[mf][nf][i] = 0.f;

    auto tile = [&](int st, int typ) -> __nv_bfloat16* {
        return hsm + (size_t)(st*4 + typ) * 128 * HROW;
    };
    auto load_stage = [&](int st, int kc) {
#pragma unroll
        for (int i = 0; i < 8; i++) {
            int idx = tid + (i << 8);          // 0..2047
            int typ = idx >> 9;
            int rem = idx & 511;
            int row = rem >> 2, unit = rem & 3;
            cp16(tile(st, typ) + row*HROW + unit*8,
                 srcs[typ] + (size_t)row * WE + kc*32 + unit*8);
        }
        cp_commit();
    };

    load_stage(0, 0);
    for (int kc = 0; kc < 16; kc++) {
        if (kc + 1 < 16) { load_stage((kc + 1) & 1, kc + 1); cp_wait<1>(); }
        else             { cp_wait<0>(); }
        __syncthreads();
        const int st = kc & 1;
        const unsigned aAh = smem_u32(tile(st, 0));
        const unsigned aAl = smem_u32(tile(st, 1));
        const unsigned aBh = smem_u32(tile(st, 2));
        const unsigned aBl = smem_u32(tile(st, 3));
#pragma unroll
        for (int ks = 0; ks < 2; ks++) {
            const int arow = wm*64 + (lane & 7) + ((lane >> 3) & 1) * 8;
            const unsigned aoff = (unsigned)(ks*2 + (lane >> 4)) * 16u;
            const int brow = wn*32 + (lane & 7);
            const unsigned boff = (unsigned)(ks*2 + ((lane >> 3) & 1)) * 16u;
            unsigned ah[4][4], al[4][4];
#pragma unroll
            for (int mf = 0; mf < 4; mf++) {
                ldsm4(ah[mf], aAh + (unsigned)(arow + mf*16) * (HROW*2) + aoff);
                ldsm4(al[mf], aAl + (unsigned)(arow + mf*16) * (HROW*2) + aoff);
            }
            unsigned bh[4][2], bl[4][2];
#pragma unroll
            for (int nf = 0; nf < 4; nf++) {
                ldsm2(bh[nf], aBh + (unsigned)(brow + nf*8) * (HROW*2) + boff);
                ldsm2(bl[nf], aBl + (unsigned)(brow + nf*8) * (HROW*2) + boff);
            }
#pragma unroll
            for (int mf = 0; mf < 4; mf++)
#pragma unroll
                for (int nf = 0; nf < 4; nf++) {
                    mma16816(acc[mf][nf], ah[mf], bh[nf]);
                    mma16816(acc[mf][nf], ah[mf], bl[nf]);
                    mma16816(acc[mf][nf], al[mf], bh[nf]);
                }
        }
        __syncthreads();
    }

    // epilogue: c frag -> C rows (lane>>2, +8), col pair (lane&3)*2
#pragma unroll
    for (int mf = 0; mf < 4; mf++) {
        const int r0 = m0 + wm*64 + mf*16 + (lane >> 2);
#pragma unroll
        for (int nf = 0; nf < 4; nf++) {
            const int c0 = n0 + wn*32 + nf*8 + (lane & 3)*2;
            const float b0 = bias[c0], b1 = bias[c0+1];
            float2 v0 = make_float2(acc[mf][nf][0] + b0, acc[mf][nf][1] + b1);
            float2 v1 = make_float2(acc[mf][nf][2] + b0, acc[mf][nf][3] + b1);
            *(float2*)&C[(size_t)r0 * WV + c0]       = v0;
            *(float2*)&C[(size_t)(r0 + 8) * WV + c0] = v1;
        }
    }
}

// ---------------- pos head: Linear(256->45) + log-softmax ----------------
__global__ void pos_head(const float* __restrict__ pouts,
                         const float* __restrict__ W, const float* __restrict__ bias,
                         float* __restrict__ out)
{
    __shared__ float sv[64];
    __shared__ float sred[2];
    int r = blockIdx.x, jt = threadIdx.x;
    const float* x = pouts + (size_t)r * PH;
    float v = 0.f;
    if (jt < PV) {
        float s = bias[jt];
        const float* w = W + (size_t)jt * PH;
#pragma unroll 4
        for (int k = 0; k < PH; k++) s += x[k] * w[k];
        v = s;
    }
    sv[jt] = v;
    __syncthreads();
    if (jt == 0) {
        float m = sv[0];
        for (int i = 1; i < PV; i++) m = fmaxf(m, sv[i]);
        float sum = 0.f;
        for (int i = 0; i < PV; i++) sum += expf(sv[i] - m);
        sred[0] = m; sred[1] = logf(sum);
    }
    __syncthreads();
    if (jt < PV) out[(size_t)r * PV + jt] = v - sred[0] - sred[1];
}

// ---------------- word log-softmax in place (vectorized) ----------------
__global__ __launch_bounds__(512) void wlogsoftmax(float* __restrict__ w)
{
    __shared__ float red[512];
    int r = blockIdx.x, tid = threadIdx.x;
    float4* row = (float4*)(w + (size_t)r * WV);
    const int NV = WV / 4;
    float m = -1e30f;
    for (int i = tid; i < NV; i += 512) {
        float4 v = row[i];
        m = fmaxf(m, fmaxf(fmaxf(v.x, v.y), fmaxf(v.z, v.w)));
    }
    red[tid] = m; __syncthreads();
    for (int s = 256; s > 0; s >>= 1) { if (tid < s) red[tid] = fmaxf(red[tid], red[tid+s]); __syncthreads(); }
    m = red[0]; __syncthreads();
    float sum = 0.f;
    for (int i = tid; i < NV; i += 512) {
        float4 v = row[i];
        sum += expf(v.x - m) + expf(v.y - m) + expf(v.z - m) + expf(v.w - m);
    }
    red[tid] = sum; __syncthreads();
    for (int s = 256; s > 0; s >>= 1) { if (tid < s) red[tid] += red[tid+s]; __syncthreads(); }
    float lg = m + logf(red[0]);
    for (int i = tid; i < NV; i += 512) {
        float4 v = row[i];
        v.x -= lg; v.y -= lg; v.z -= lg; v.w -= lg;
        row[i] = v;
    }
}

// ---------------- launch ----------------
extern "C" void kernel_launch(void* const* d_in, const int* in_sizes, int n_in,
                              void* d_out, int out_size)
{
    const int*   pos      = (const int*)d_in[0];
    const int*   word     = (const int*)d_in[1];
    const float* pos_emb  = (const float*)d_in[2];
    const float* word_emb = (const float*)d_in[3];
    const float* pWih     = (const float*)d_in[4];
    const float* pWhh     = (const float*)d_in[5];
    const float* pbih     = (const float*)d_in[6];
    const float* pbhh     = (const float*)d_in[7];
    const float* w0Wih    = (const float*)d_in[8];
    const float* w0Whh    = (const float*)d_in[9];
    const float* w0bih    = (const float*)d_in[10];
    const float* w0bhh    = (const float*)d_in[11];
    const float* w1Wih    = (const float*)d_in[12];
    const float* w1Whh    = (const float*)d_in[13];
    const float* w1bih    = (const float*)d_in[14];
    const float* w1bhh    = (const float*)d_in[15];
    const float* pprojW   = (const float*)d_in[16];
    const float* pprojb   = (const float*)d_in[17];
    const float* wp1W     = (const float*)d_in[18];
    const float* wp1b     = (const float*)d_in[19];
    const float* wp2b     = (const float*)d_in[20];

    float *pA, *pA0, *ph, *wh1, *wmid;
    __nv_bfloat16 *embH, *embL, *midH, *midL;
    cudaGetSymbolAddress((void**)&pA,   g_Apos);
    cudaGetSymbolAddress((void**)&pA0,  g_Aw0);
    cudaGetSymbolAddress((void**)&ph,   g_ph);
    cudaGetSymbolAddress((void**)&wh1,  g_wh1);
    cudaGetSymbolAddress((void**)&wmid, g_wmid);
    cudaGetSymbolAddress((void**)&embH, g_embH);
    cudaGetSymbolAddress((void**)&embL, g_embL);
    cudaGetSymbolAddress((void**)&midH, g_midH);
    cudaGetSymbolAddress((void**)&midL, g_midL);

    const int smem_rec = 2 * 2 * 8 * 32 * 32 * 4;        // 131072 B
    cudaFuncSetAttribute(recurrence, cudaFuncAttributeMaxDynamicSharedMemorySize, smem_rec);
    const int smem_head = 2 * 4 * 128 * HROW * 2;        // 81920 B
    cudaFuncSetAttribute(head_mma, cudaFuncAttributeMaxDynamicSharedMemorySize, smem_head);

    zero_init<<<(Bb*WH + 255) / 256, 256>>>();

    // precompute input projections (+ both biases) for all (t,b) rows
    gemm_nt<<<dim3(4*PH/64, Tt*Bb/64), 256>>>(pos_emb, pos, PE, pWih, PE+WH,
                                              pA, 4*PH, PE, pbih, pbhh);
    gemm_nt<<<dim3(4*WH/64, Tt*Bb/64), 256>>>(word_emb, word, WE, w0Wih, WE+PH,
                                              pA0, 4*WH, WE, w0bih, w0bhh);

    // embedding bf16 hi/lo split (independent of recurrence)
    cvt_hilo<<<(WV*WE + 255)/256, 256>>>(word_emb, embH, embL, WV*WE);

    // whole recurrence in one persistent kernel
    recurrence<<<GRID, 512, smem_rec>>>(pA, pA0, pWih, pWhh,
                                        w0Wih, w0Whh, w1Wih, w1Whh,
                                        w1bih, w1bhh);

    float* out  = (float*)d_out;
    float* wout = out + (size_t)Tt * Bb * PV;

    // w_mid = w_outs @ wp1_W^T + wp1_b  (fp32), then hi/lo split
    gemm_nt<<<dim3(WE/64, Tt*Bb/64), 256>>>(wh1 + (size_t)Bb * WH, nullptr, WH,
                                            wp1W, WH, wmid, WE, WH, wp1b, nullptr);
    cvt_hilo<<<(Tt*Bb*WE + 255)/256, 256>>>(wmid, midH, midL, Tt*Bb*WE);

    // word logits via bf16-split mma.sync GEMM, directly into d_out
    head_mma<<<dim3(Tt*Bb/128, WV/128), 256, smem_head>>>(midH, midL, embH, embL,
                                                          wp2b, wout);

    // pos head (fused log-softmax)
    pos_head<<<Tt*Bb, 64>>>(ph + (size_t)Bb * PH, pprojW, pprojb, out);
    // word log-softmax in place
    wlogsoftmax<<<Tt*Bb, 512>>>(wout);
}

// round 15
// speedup vs baseline: 1.3104x; 1.3104x over previous
#include <cuda_runtime.h>
#include <cuda_bf16.h>
#include <math.h>

#define Tt 128
#define Bb 32
#define PH 256
#define WH 1024
#define PV 45
#define WV 32000
#define PE 64
#define WE 512
#define GRID 128

// ---------------- device scratch (no allocations) ----------------
__device__ float g_Apos[Tt*Bb*4*PH];
__device__ float g_Aw0 [Tt*Bb*4*WH];
__device__ float g_ph  [(Tt+1)*Bb*PH];
__device__ float g_wh0 [(Tt+1)*Bb*WH];
__device__ float g_wh1 [(Tt+1)*Bb*WH];
__device__ float g_pc  [Bb*PH];
__device__ float g_wc0 [Bb*WH];
__device__ float g_wc1 [Bb*WH];
__device__ float g_wmid[Tt*Bb*WE];
__device__ __nv_bfloat16 g_embH[WV*WE];
__device__ __nv_bfloat16 g_embL[WV*WE];
__device__ __nv_bfloat16 g_midH[Tt*Bb*WE];
__device__ __nv_bfloat16 g_midL[Tt*Bb*WE];
__device__ unsigned g_cnt;
__device__ volatile unsigned g_gen;

// ---------------- generic helpers ----------------
__device__ __forceinline__ unsigned long long fma2(unsigned long long a,
                                                   unsigned long long b,
                                                   unsigned long long c) {
    unsigned long long d;
    asm("fma.rn.f32x2 %0, %1, %2, %3;" : "=l"(d) : "l"(a), "l"(b), "l"(c));
    return d;
}
__device__ __forceinline__ float acc_sum(unsigned long long v) {
    float x, y;
    asm("mov.b64 {%0,%1}, %2;" : "=f"(x), "=f"(y) : "l"(v));
    return x + y;
}
__device__ __forceinline__ float sigf(float x) { return 1.0f / (1.0f + expf(-x)); }

__device__ __forceinline__ void cp16(void* s, const void* g) {
    unsigned ss = (unsigned)__cvta_generic_to_shared(s);
    asm volatile("cp.async.cg.shared.global [%0], [%1], 16;" :: "r"(ss), "l"(g));
}
__device__ __forceinline__ void cp_commit() {
    asm volatile("cp.async.commit_group;" ::: "memory");
}
template <int N> __device__ __forceinline__ void cp_wait() {
    asm volatile("cp.async.wait_group %0;" :: "n"(N) : "memory");
}
__device__ __forceinline__ unsigned smem_u32(const void* p) {
    return (unsigned)__cvta_generic_to_shared(p);
}

// mma.sync bf16 + ldmatrix (non-arch-gated tensor path, works on sm_103)
__device__ __forceinline__ void ldsm4(unsigned r[4], unsigned addr) {
    asm volatile("ldmatrix.sync.aligned.m8n8.x4.shared.b16 {%0,%1,%2,%3}, [%4];"
        : "=r"(r[0]), "=r"(r[1]), "=r"(r[2]), "=r"(r[3]) : "r"(addr));
}
__device__ __forceinline__ void ldsm2(unsigned r[2], unsigned addr) {
    asm volatile("ldmatrix.sync.aligned.m8n8.x2.shared.b16 {%0,%1}, [%2];"
        : "=r"(r[0]), "=r"(r[1]) : "r"(addr));
}
__device__ __forceinline__ void mma16816(float c[4], const unsigned a[4], const unsigned b[2]) {
    asm volatile("mma.sync.aligned.m16n8k16.row.col.f32.bf16.bf16.f32 "
        "{%0,%1,%2,%3}, {%4,%5,%6,%7}, {%8,%9}, {%0,%1,%2,%3};"
        : "+f"(c[0]), "+f"(c[1]), "+f"(c[2]), "+f"(c[3])
        : "r"(a[0]), "r"(a[1]), "r"(a[2]), "r"(a[3]), "r"(b[0]), "r"(b[1]));
}

// sense-reversing grid barrier (all GRID CTAs co-resident: 1 CTA/SM)
__device__ __forceinline__ void gsync() {
    __syncthreads();
    if (threadIdx.x == 0) {
        unsigned gen = g_gen;
        __threadfence();
        if (atomicAdd(&g_cnt, 1u) == GRID - 1u) {
            g_cnt = 0u;
            __threadfence();
            g_gen = gen + 1u;
        } else {
            while (g_gen == gen) { }
        }
        __threadfence();
    }
    __syncthreads();
}

// ---------------- init ----------------
__global__ void zero_init() {
    int i = blockIdx.x * blockDim.x + threadIdx.x;
    if (i == 0) { g_cnt = 0u; g_gen = 0u; }
    if (i < Bb*PH) { g_ph[i] = 0.f; g_pc[i] = 0.f; }
    if (i < Bb*WH) { g_wh0[i] = 0.f; g_wh1[i] = 0.f; g_wc0[i] = 0.f; g_wc1[i] = 0.f; }
}

// ---------------- fp32 -> bf16 hi/lo split ----------------
__global__ void cvt_hilo(const float* __restrict__ src,
                         __nv_bfloat16* __restrict__ hi,
                         __nv_bfloat16* __restrict__ lo, int n)
{
    int i = blockIdx.x * blockDim.x + threadIdx.x;
    if (i < n) {
        float v = src[i];
        __nv_bfloat16 h = __float2bfloat16(v);
        hi[i] = h;
        lo[i] = __float2bfloat16(v - __bfloat162float(h));
    }
}

// ---------------- 4-stage pipelined NT GEMM (fp32, for precompute/wmid) ----------------
__global__ __launch_bounds__(256) void gemm_nt(
    const float* __restrict__ A, const int* __restrict__ gather, int lda,
    const float* __restrict__ Bm, int ldb,
    float* __restrict__ C, int ldc, int K,
    const float* __restrict__ bias1, const float* __restrict__ bias2)
{
    constexpr int S = 4;
    __shared__ __align__(16) float As[S][64][20];
    __shared__ __align__(16) float Bs[S][64][20];
    const int tid = threadIdx.x;
    const int m0 = blockIdx.y * 64, n0 = blockIdx.x * 64;
    const int tn = tid & 15, tm = tid >> 4;
    const int lrow = tid >> 2, lks = tid & 3;
    const int agr = gather ? gather[m0 + lrow] : (m0 + lrow);
    const float* aptr = A  + (size_t)agr * lda + lks * 4;
    const float* bptr = Bm + (size_t)(n0 + lrow) * ldb + lks * 4;

    unsigned long long acc[4][4];
#pragma unroll
    for (int r = 0; r < 4; r++)
#pragma unroll
        for (int s = 0; s < 4; s++) acc[r][s] = 0ull;

    const int nch = K >> 4;
#pragma unroll
    for (int i = 0; i < S - 1; i++) {
        if (i < nch) {
            cp16(&As[i][lrow][lks*4], aptr + i*16);
            cp16(&Bs[i][lrow][lks*4], bptr + i*16);
        }
        cp_commit();
    }

    for (int ci = 0; ci < nch; ci++) {
        if (ci + S - 1 < nch) {
            const int b = (ci + S - 1) & (S - 1);
            cp16(&As[b][lrow][lks*4], aptr + (ci + S - 1)*16);
            cp16(&Bs[b][lrow][lks*4], bptr + (ci + S - 1)*16);
            cp_commit();
            cp_wait<S-1>();
        } else {
            cp_wait<0>();
        }
        __syncthreads();
        const int bf = ci & (S - 1);
#pragma unroll
        for (int kk = 0; kk < 16; kk += 4) {
            ulonglong2 av[4], bv[4];
#pragma unroll
            for (int r = 0; r < 4; r++) av[r] = *(const ulonglong2*)&As[bf][tm*4 + r][kk];
#pragma unroll
            for (int s = 0; s < 4; s++) bv[s] = *(const ulonglong2*)&Bs[bf][tn + 16*s][kk];
#pragma unroll
            for (int r = 0; r < 4; r++)
#pragma unroll
                for (int s = 0; s < 4; s++) {
                    acc[r][s] = fma2(av[r].x, bv[s].x, acc[r][s]);
                    acc[r][s] = fma2(av[r].y, bv[s].y, acc[r][s]);
                }
        }
        __syncthreads();
    }
#pragma unroll
    for (int s = 0; s < 4; s++) {
        int n = n0 + tn + 16*s;
        float badd = 0.f;
        if (bias1) badd += bias1[n];
        if (bias2) badd += bias2[n];
#pragma unroll
        for (int r = 0; r < 4; r++) {
            int m = m0 + tm*4 + r;
            C[(size_t)m * ldc + n] = acc_sum(acc[r][s]) + badd;
        }
    }
}

// ---------------- LSTM cell phase (R12-verified): outer-product warps, 8-way k-split ----
// CTA owns 32 gate cols (8 h x 4 gates). 256 threads = 8 warps, each warp owns
// the FULL 32x32 C tile over its k-region (nch/8 chunks of 32k).
// lane = rg(8 row-groups) x cg(4 col-groups); thread tile 4 rows x 8 cols.
__device__ __noinline__ void cell_phase(
    float* smem,
    const float* pre, const float* bih, const float* bhh,
    const float* x0, int ldx0, const float* W0, int ldW0, int K0,
    const float* x1, int ldx1, const float* W1, int ldW1, int K1,
    float* c_st, float* h_out, int H)
{
    const int cta = blockIdx.x;
    if (cta * 8 >= H) return;
    const int tid  = threadIdx.x;
    const int lane = tid & 31;
    const int wid  = tid >> 5;
    const int rg   = lane >> 2;       // row group 0..7 (rows rg*4..rg*4+3)
    const int cg   = lane & 3;        // col group 0..3 (cols cg*8..cg*8+7)

    float* xs = smem;                  // [2][8][32][32]
    float* ws = smem + 2*8*32*32;      // [2][8][32][32]

    const int nc0 = K0 >> 5;
    const int nch = nc0 + (K1 >> 5);
    const int cpw = nch >> 3;          // chunks per warp

    // preload pre/bias for this thread's pointwise element (b, h)
    const int pb = tid >> 3, phh = tid & 7;
    const int hmy = cta * 8 + phh;
    float pv[4];
#pragma unroll
    for (int gt = 0; gt < 4; gt++) {
        if (pre) pv[gt] = pre[(size_t)pb * (4*H) + gt*H + hmy];
        else     pv[gt] = bih[gt*H + hmy] + bhh[gt*H + hmy];
    }

    unsigned long long acc[4][8];
#pragma unroll
    for (int r = 0; r < 4; r++)
#pragma unroll
        for (int c = 0; c < 8; c++) acc[r][c] = 0ull;

    auto load_stage = [&](int st, int cs) {
#pragma unroll
        for (int i = 0; i < 8; i++) {
            int idx = tid + (i << 8);          // 0..2047
            int wslot = idx >> 8;
            int rem = idx & 255;
            int row = rem >> 3, ks = rem & 7;
            int ci = wslot * cpw + cs;
            const float* xp; const float* Wp; int ldx, ldW, k0;
            if (ci < nc0) { xp = x0; Wp = W0; ldx = ldx0; ldW = ldW0; k0 = ci << 5; }
            else          { xp = x1; Wp = W1; ldx = ldx1; ldW = ldW1; k0 = (ci - nc0) << 5; }
            cp16(&xs[((st*8 + wslot)*32 + row)*32 + ((ks ^ (row >> 2)) << 2)],
                 xp + (size_t)row * ldx + k0 + (ks << 2));
            int jr = (row >> 3) * H + cta * 8 + (row & 7);   // row as col index
            cp16(&ws[((st*8 + wslot)*32 + row)*32 + ((ks ^ (row >> 3)) << 2)],
                 Wp + (size_t)jr * ldW + k0 + (ks << 2));
        }
        cp_commit();
    };

    load_stage(0, 0);
    for (int cs = 0; cs < cpw; cs++) {
        if (cs + 1 < cpw) { load_stage((cs + 1) & 1, cs + 1); cp_wait<1>(); }
        else              { cp_wait<0>(); }
        __syncthreads();
        const int st = cs & 1;
        const float* xb = &xs[((st*8 + wid)*32)*32];
        const float* wb = &ws[((st*8 + wid)*32)*32];
#pragma unroll
        for (int kkq = 0; kkq < 8; kkq++) {
            ulonglong2 xv[4];
#pragma unroll
            for (int r = 0; r < 4; r++)
                xv[r] = *(const ulonglong2*)&xb[(rg*4 + r)*32 + ((kkq ^ rg) << 2)];
#pragma unroll
            for (int c = 0; c < 8; c++) {
                ulonglong2 wv = *(const ulonglong2*)&wb[(cg*8 + c)*32 + ((kkq ^ cg) << 2)];
#pragma unroll
                for (int r = 0; r < 4; r++) {
                    acc[r][c] = fma2(xv[r].x, wv.x, acc[r][c]);
                    acc[r][c] = fma2(xv[r].y, wv.y, acc[r][c]);
                }
            }
        }
        __syncthreads();
    }

    // deterministic 8-way k-reduction through smem (stride 33), then pointwise
    float* red = smem;   // overlay; mainloop ended with __syncthreads
#pragma unroll
    for (int r = 0; r < 4; r++)
#pragma unroll
        for (int c = 0; c < 8; c++)
            red[(wid*32 + rg*4 + r)*33 + cg*8 + c] = acc_sum(acc[r][c]);
    __syncthreads();

    {
        float g4[4];
#pragma unroll
        for (int gt = 0; gt < 4; gt++) {
            int col = gt*8 + phh;
            float v = 0.f;
#pragma unroll
            for (int w = 0; w < 8; w++) v += red[(w*32 + pb)*33 + col];
            g4[gt] = v + pv[gt];
        }
        float cp = c_st[pb*H + hmy];
        float cn = sigf(g4[1]) * cp + sigf(g4[0]) * tanhf(g4[2]);
        c_st[pb*H + hmy]  = cn;
        h_out[pb*H + hmy] = sigf(g4[3]) * tanhf(cn);
    }
    __syncthreads();   // protect overlay before next phase's loads
}

// ---------------- persistent recurrence kernel ----------------
__global__ __launch_bounds__(256, 1) void recurrence(
    const float* __restrict__ pre_pos, const float* __restrict__ pre_w0,
    const float* __restrict__ pWih,  const float* __restrict__ pWhh,
    const float* __restrict__ w0Wih, const float* __restrict__ w0Whh,
    const float* __restrict__ w1Wih, const float* __restrict__ w1Whh,
    const float* __restrict__ w1bih, const float* __restrict__ w1bhh)
{
    extern __shared__ float smem[];
    for (int t = 0; t < Tt; t++) {
        cell_phase(smem, pre_pos + (size_t)t * Bb * 4 * PH, nullptr, nullptr,
                   g_wh1 + (size_t)t * Bb * WH, WH, pWih + PE, PE + WH, WH,
                   g_ph  + (size_t)t * Bb * PH, PH, pWhh,      PH,      PH,
                   g_pc, g_ph + (size_t)(t+1) * Bb * PH, PH);
        gsync();
        cell_phase(smem, pre_w0 + (size_t)t * Bb * 4 * WH, nullptr, nullptr,
                   g_ph  + (size_t)(t+1) * Bb * PH, PH, w0Wih + WE, WE + PH, PH,
                   g_wh0 + (size_t)t * Bb * WH,     WH, w0Whh,      WH,      WH,
                   g_wc0, g_wh0 + (size_t)(t+1) * Bb * WH, WH);
        gsync();
        cell_phase(smem, nullptr, w1bih, w1bhh,
                   g_wh0 + (size_t)(t+1) * Bb * WH, WH, w1Wih, WH, WH,
                   g_wh1 + (size_t)t * Bb * WH,     WH, w1Whh, WH, WH,
                   g_wc1, g_wh1 + (size_t)(t+1) * Bb * WH, WH);
        gsync();
    }
}

// ---------------- bf16 mma.sync head GEMM ----------------
// C[4096, 32000] = A . B^T + bias via 3-term hi/lo split (Ah.Bh + Ah.Bl + Al.Bh).
// CTA tile 128x128, 8 warps (2m x 4n), warp tile 64x32 (m16n8k16 frags 4x4).
// K chunks of 32, double-buffered cp.async; smem rows padded to 80B so every
// ldmatrix phase is bank-conflict-free. Grid (m=32, n=250), m-fastest for B reuse.
#define HROW 40
__global__ __launch_bounds__(256) void head_mma(
    const __nv_bfloat16* __restrict__ Ah, const __nv_bfloat16* __restrict__ Al,
    const __nv_bfloat16* __restrict__ Bh, const __nv_bfloat16* __restrict__ Bl,
    const float* __restrict__ bias, float* __restrict__ C)
{
    extern __shared__ __align__(16) __nv_bfloat16 hsm[];
    const int tid = threadIdx.x, lane = tid & 31, wid = tid >> 5;
    const int wm = wid >> 2, wn = wid & 3;
    const int m0 = blockIdx.x * 128, n0 = blockIdx.y * 128;

    const __nv_bfloat16* srcs[4] = { Ah + (size_t)m0 * WE, Al + (size_t)m0 * WE,
                                     Bh + (size_t)n0 * WE, Bl + (size_t)n0 * WE };

    float acc[4][4][4];
#pragma unroll
    for (int mf = 0; mf < 4; mf++)
#pragma unroll
        for (int nf = 0; nf < 4; nf++)
#pragma unroll
            for (int i = 0; i < 4; i++) acc[mf][nf][i] = 0.f;

    auto tile = [&](int st, int typ) -> __nv_bfloat16* {
        return hsm + (size_t)(st*4 + typ) * 128 * HROW;
    };
    auto load_stage = [&](int st, int kc) {
#pragma unroll
        for (int i = 0; i < 8; i++) {
            int idx = tid + (i << 8);          // 0..2047
            int typ = idx >> 9;
            int rem = idx & 511;
            int row = rem >> 2, unit = rem & 3;
            cp16(tile(st, typ) + row*HROW + unit*8,
                 srcs[typ] + (size_t)row * WE + kc*32 + unit*8);
        }
        cp_commit();
    };

    load_stage(0, 0);
    for (int kc = 0; kc < 16; kc++) {
        if (kc + 1 < 16) { load_stage((kc + 1) & 1, kc + 1); cp_wait<1>(); }
        else             { cp_wait<0>(); }
        __syncthreads();
        const int st = kc & 1;
        const unsigned aAh = smem_u32(tile(st, 0));
        const unsigned aAl = smem_u32(tile(st, 1));
        const unsigned aBh = smem_u32(tile(st, 2));
        const unsigned aBl = smem_u32(tile(st, 3));
#pragma unroll
        for (int ks = 0; ks < 2; ks++) {
            const int arow = wm*64 + (lane & 7) + ((lane >> 3) & 1) * 8;
            const unsigned aoff = (unsigned)(ks*2 + (lane >> 4)) * 16u;
            const int brow = wn*32 + (lane & 7);
            const unsigned boff = (unsigned)(ks*2 + ((lane >> 3) & 1)) * 16u;
            unsigned ah[4][4], al[4][4];
#pragma unroll
            for (int mf = 0; mf < 4; mf++) {
                ldsm4(ah[mf], aAh + (unsigned)(arow + mf*16) * (HROW*2) + aoff);
                ldsm4(al[mf], aAl + (unsigned)(arow + mf*16) * (HROW*2) + aoff);
            }
            unsigned bh[4][2], bl[4][2];
#pragma unroll
            for (int nf = 0; nf < 4; nf++) {
                ldsm2(bh[nf], aBh + (unsigned)(brow + nf*8) * (HROW*2) + boff);
                ldsm2(bl[nf], aBl + (unsigned)(brow + nf*8) * (HROW*2) + boff);
            }
#pragma unroll
            for (int mf = 0; mf < 4; mf++)
#pragma unroll
                for (int nf = 0; nf < 4; nf++) {
                    mma16816(acc[mf][nf], ah[mf], bh[nf]);
                    mma16816(acc[mf][nf], ah[mf], bl[nf]);
                    mma16816(acc[mf][nf], al[mf], bh[nf]);
                }
        }
        __syncthreads();
    }

    // epilogue: c frag -> C rows (lane>>2, +8), col pair (lane&3)*2
#pragma unroll
    for (int mf = 0; mf < 4; mf++) {
        const int r0 = m0 + wm*64 + mf*16 + (lane >> 2);
#pragma unroll
        for (int nf = 0; nf < 4; nf++) {
            const int c0 = n0 + wn*32 + nf*8 + (lane & 3)*2;
            const float b0 = bias[c0], b1 = bias[c0+1];
            float2 v0 = make_float2(acc[mf][nf][0] + b0, acc[mf][nf][1] + b1);
            float2 v1 = make_float2(acc[mf][nf][2] + b0, acc[mf][nf][3] + b1);
            *(float2*)&C[(size_t)r0 * WV + c0]       = v0;
            *(float2*)&C[(size_t)(r0 + 8) * WV + c0] = v1;
        }
    }
}

// ---------------- pos head: Linear(256->45) + log-softmax ----------------
__global__ void pos_head(const float* __restrict__ pouts,
                         const float* __restrict__ W, const float* __restrict__ bias,
                         float* __restrict__ out)
{
    __shared__ float sv[64];
    __shared__ float sred[2];
    int r = blockIdx.x, jt = threadIdx.x;
    const float* x = pouts + (size_t)r * PH;
    float v = 0.f;
    if (jt < PV) {
        float s = bias[jt];
        const float* w = W + (size_t)jt * PH;
#pragma unroll 4
        for (int k = 0; k < PH; k++) s += x[k] * w[k];
        v = s;
    }
    sv[jt] = v;
    __syncthreads();
    if (jt == 0) {
        float m = sv[0];
        for (int i = 1; i < PV; i++) m = fmaxf(m, sv[i]);
        float sum = 0.f;
        for (int i = 0; i < PV; i++) sum += expf(sv[i] - m);
        sred[0] = m; sred[1] = logf(sum);
    }
    __syncthreads();
    if (jt < PV) out[(size_t)r * PV + jt] = v - sred[0] - sred[1];
}

// ---------------- word log-softmax in place (vectorized) ----------------
__global__ __launch_bounds__(512) void wlogsoftmax(float* __restrict__ w)
{
    __shared__ float red[512];
    int r = blockIdx.x, tid = threadIdx.x;
    float4* row = (float4*)(w + (size_t)r * WV);
    const int NV = WV / 4;
    float m = -1e30f;
    for (int i = tid; i < NV; i += 512) {
        float4 v = row[i];
        m = fmaxf(m, fmaxf(fmaxf(v.x, v.y), fmaxf(v.z, v.w)));
    }
    red[tid] = m; __syncthreads();
    for (int s = 256; s > 0; s >>= 1) { if (tid < s) red[tid] = fmaxf(red[tid], red[tid+s]); __syncthreads(); }
    m = red[0]; __syncthreads();
    float sum = 0.f;
    for (int i = tid; i < NV; i += 512) {
        float4 v = row[i];
        sum += expf(v.x - m) + expf(v.y - m) + expf(v.z - m) + expf(v.w - m);
    }
    red[tid] = sum; __syncthreads();
    for (int s = 256; s > 0; s >>= 1) { if (tid < s) red[tid] += red[tid+s]; __syncthreads(); }
    float lg = m + logf(red[0]);
    for (int i = tid; i < NV; i += 512) {
        float4 v = row[i];
        v.x -= lg; v.y -= lg; v.z -= lg; v.w -= lg;
        row[i] = v;
    }
}

// ---------------- launch ----------------
extern "C" void kernel_launch(void* const* d_in, const int* in_sizes, int n_in,
                              void* d_out, int out_size)
{
    const int*   pos      = (const int*)d_in[0];
    const int*   word     = (const int*)d_in[1];
    const float* pos_emb  = (const float*)d_in[2];
    const float* word_emb = (const float*)d_in[3];
    const float* pWih     = (const float*)d_in[4];
    const float* pWhh     = (const float*)d_in[5];
    const float* pbih     = (const float*)d_in[6];
    const float* pbhh     = (const float*)d_in[7];
    const float* w0Wih    = (const float*)d_in[8];
    const float* w0Whh    = (const float*)d_in[9];
    const float* w0bih    = (const float*)d_in[10];
    const float* w0bhh    = (const float*)d_in[11];
    const float* w1Wih    = (const float*)d_in[12];
    const float* w1Whh    = (const float*)d_in[13];
    const float* w1bih    = (const float*)d_in[14];
    const float* w1bhh    = (const float*)d_in[15];
    const float* pprojW   = (const float*)d_in[16];
    const float* pprojb   = (const float*)d_in[17];
    const float* wp1W     = (const float*)d_in[18];
    const float* wp1b     = (const float*)d_in[19];
    const float* wp2b     = (const float*)d_in[20];

    float *pA, *pA0, *ph, *wh1, *wmid;
    __nv_bfloat16 *embH, *embL, *midH, *midL;
    cudaGetSymbolAddress((void**)&pA,   g_Apos);
    cudaGetSymbolAddress((void**)&pA0,  g_Aw0);
    cudaGetSymbolAddress((void**)&ph,   g_ph);
    cudaGetSymbolAddress((void**)&wh1,  g_wh1);
    cudaGetSymbolAddress((void**)&wmid, g_wmid);
    cudaGetSymbolAddress((void**)&embH, g_embH);
    cudaGetSymbolAddress((void**)&embL, g_embL);
    cudaGetSymbolAddress((void**)&midH, g_midH);
    cudaGetSymbolAddress((void**)&midL, g_midL);

    const int smem_rec = 2 * 2 * 8 * 32 * 32 * 4;        // 131072 B
    cudaFuncSetAttribute(recurrence, cudaFuncAttributeMaxDynamicSharedMemorySize, smem_rec);
    const int smem_head = 2 * 4 * 128 * HROW * 2;        // 81920 B
    cudaFuncSetAttribute(head_mma, cudaFuncAttributeMaxDynamicSharedMemorySize, smem_head);

    zero_init<<<(Bb*WH + 255) / 256, 256>>>();

    // precompute input projections (+ both biases) for all (t,b) rows
    gemm_nt<<<dim3(4*PH/64, Tt*Bb/64), 256>>>(pos_emb, pos, PE, pWih, PE+WH,
                                              pA, 4*PH, PE, pbih, pbhh);
    gemm_nt<<<dim3(4*WH/64, Tt*Bb/64), 256>>>(word_emb, word, WE, w0Wih, WE+PH,
                                              pA0, 4*WH, WE, w0bih, w0bhh);

    // embedding bf16 hi/lo split (independent of recurrence)
    cvt_hilo<<<(WV*WE + 255)/256, 256>>>(word_emb, embH, embL, WV*WE);

    // whole recurrence in one persistent kernel (R12-verified 8-warp version)
    recurrence<<<GRID, 256, smem_rec>>>(pA, pA0, pWih, pWhh,
                                        w0Wih, w0Whh, w1Wih, w1Whh,
                                        w1bih, w1bhh);

    float* out  = (float*)d_out;
    float* wout = out + (size_t)Tt * Bb * PV;

    // w_mid = w_outs @ wp1_W^T + wp1_b  (fp32), then hi/lo split
    gemm_nt<<<dim3(WE/64, Tt*Bb/64), 256>>>(wh1 + (size_t)Bb * WH, nullptr, WH,
                                            wp1W, WH, wmid, WE, WH, wp1b, nullptr);
    cvt_hilo<<<(Tt*Bb*WE + 255)/256, 256>>>(wmid, midH, midL, Tt*Bb*WE);

    // word logits via bf16-split mma.sync GEMM, directly into d_out
    head_mma<<<dim3(Tt*Bb/128, WV/128), 256, smem_head>>>(midH, midL, embH, embL,
                                                          wp2b, wout);

    // pos head (fused log-softmax)
    pos_head<<<Tt*Bb, 64>>>(ph + (size_t)Bb * PH, pprojW, pprojb, out);
    // word log-softmax in place
    wlogsoftmax<<<Tt*Bb, 512>>>(wout);
}